// round 1
// baseline (speedup 1.0000x reference)
#include <cuda_runtime.h>
#include <math.h>

#define B 8
#define S 1024
#define D 512
#define H 8
#define DK 64

#define TM 32          // query rows per attention block
#define BJ 128         // key/value tile width
#define SS_STRIDE 1028 // 1024 + 4 (keeps 16B alignment, breaks bank alignment)
#define SQ_STRIDE 68
#define SKT_STRIDE 132
#define SV_STRIDE 68

// scratch (device globals; no allocation allowed)
__device__ float g_qk[B*H*S*DK];   // 16 MB, q == k (kq_same)
__device__ float g_v [B*H*S*DK];   // 16 MB
__device__ float g_attn[B*S*D];    // 16 MB, attention output pre-projection

// ---------------------------------------------------------------------------
// Kernel 1: fused QK / V projection.  y = x @ W^T + b, written head-split
// [b,h,s,dk].  blockIdx.z selects (Wk,bk)->g_qk or (Wv,bv)->g_v.
// 64x64 tiles, BK=16, 256 threads, 4x4 micro-tiles.
// ---------------------------------------------------------------------------
__global__ __launch_bounds__(256) void proj_kernel(
    const float* __restrict__ x,
    const float* __restrict__ Wk, const float* __restrict__ bk,
    const float* __restrict__ Wv, const float* __restrict__ bv)
{
    __shared__ float sA[16*68];
    __shared__ float sB[16*68];

    const float* W    = blockIdx.z ? Wv : Wk;
    const float* bias = blockIdx.z ? bv : bk;
    float* dst        = blockIdx.z ? g_v : g_qk;

    const int m0 = blockIdx.y * 64;
    const int n0 = blockIdx.x * 64;
    const int tid = threadIdx.x;
    const int tx = tid & 15;      // n micro-group
    const int ty = tid >> 4;      // m micro-group
    const int lrow = tid >> 2;    // 0..63 load row
    const int lc4  = tid & 3;     // 0..3  load float4 column

    float acc[4][4] = {};

    for (int k0 = 0; k0 < D; k0 += 16) {
        float4 av = *(const float4*)(x + (long)(m0 + lrow)*D + k0 + lc4*4);
        float4 bw = *(const float4*)(W + (long)(n0 + lrow)*D + k0 + lc4*4);
        __syncthreads();
        sA[(lc4*4+0)*68 + lrow] = av.x;
        sA[(lc4*4+1)*68 + lrow] = av.y;
        sA[(lc4*4+2)*68 + lrow] = av.z;
        sA[(lc4*4+3)*68 + lrow] = av.w;
        sB[(lc4*4+0)*68 + lrow] = bw.x;
        sB[(lc4*4+1)*68 + lrow] = bw.y;
        sB[(lc4*4+2)*68 + lrow] = bw.z;
        sB[(lc4*4+3)*68 + lrow] = bw.w;
        __syncthreads();
        #pragma unroll
        for (int kk = 0; kk < 16; ++kk) {
            float4 a4 = *(const float4*)(sA + kk*68 + ty*4);
            float4 b4 = *(const float4*)(sB + kk*68 + tx*4);
            acc[0][0] += a4.x*b4.x; acc[0][1] += a4.x*b4.y; acc[0][2] += a4.x*b4.z; acc[0][3] += a4.x*b4.w;
            acc[1][0] += a4.y*b4.x; acc[1][1] += a4.y*b4.y; acc[1][2] += a4.y*b4.z; acc[1][3] += a4.y*b4.w;
            acc[2][0] += a4.z*b4.x; acc[2][1] += a4.z*b4.y; acc[2][2] += a4.z*b4.z; acc[2][3] += a4.z*b4.w;
            acc[3][0] += a4.w*b4.x; acc[3][1] += a4.w*b4.y; acc[3][2] += a4.w*b4.z; acc[3][3] += a4.w*b4.w;
        }
    }

    // epilogue: add bias, scatter to [b,h,s,dk]
    const int n = n0 + tx*4;           // hh fixed per block (n0 mult of 64)
    const int hh = n >> 6;
    const int dd = n & 63;
    float4 bia = *(const float4*)(bias + n);
    #pragma unroll
    for (int r = 0; r < 4; ++r) {
        int m = m0 + ty*4 + r;
        int bb = m >> 10, ss = m & 1023;
        float4 v;
        v.x = acc[r][0] + bia.x;
        v.y = acc[r][1] + bia.y;
        v.z = acc[r][2] + bia.z;
        v.w = acc[r][3] + bia.w;
        *(float4*)(dst + (((long)bb*H + hh)*S + ss)*DK + dd) = v;
    }
}

// ---------------------------------------------------------------------------
// Kernel 2: attention with distance decay.  One block = 32 query rows of one
// (b,h).  Scores held entirely in SMEM (32 x 1024).
// ---------------------------------------------------------------------------
__global__ __launch_bounds__(256) void attn_kernel(
    const float* __restrict__ utT, const float* __restrict__ gammas)
{
    extern __shared__ float smem[];
    float* sS  = smem;                         // TM * SS_STRIDE
    float* sQ  = sS + TM*SS_STRIDE;            // TM * SQ_STRIDE
    float* sKV = sQ + TM*SQ_STRIDE;            // max(64*132, 128*68)

    const int i0  = blockIdx.x * TM;
    const int h   = blockIdx.y;
    const int b   = blockIdx.z;
    const int tid = threadIdx.x;
    const long bh = (long)(b*H + h);
    const float* Kbase = g_qk + bh * (long)(S*DK);
    const float* Vbase = g_v  + bh * (long)(S*DK);

    // ---- load Q tile (32 x 64) ----
    #pragma unroll
    for (int it = 0; it < 2; ++it) {
        int idx = tid + it*256;          // 0..511 = 32 rows * 16 float4
        int row = idx >> 4, c4 = idx & 15;
        float4 v = *(const float4*)(Kbase + (long)(i0 + row)*DK + c4*4);
        *(float4*)(sQ + row*SQ_STRIDE + c4*4) = v;
    }

    const int TJn = (i0 + TM + BJ - 1) / BJ;   // key tiles needed (causal)

    // ---- score GEMM: sS[i][j] = (q_i . k_j) / 8 * utT[b,i,j] ----
    const int ty = tid >> 5;   // 0..7  -> 4 rows each
    const int tx = tid & 31;   // 0..31 -> 4 cols each
    const float inv_scale = 0.125f;  // 1/sqrt(64)

    for (int jt = 0; jt < TJn; ++jt) {
        __syncthreads();
        // load K tile transposed: sKV[dk][j], 128 keys
        #pragma unroll
        for (int it = 0; it < 8; ++it) {
            int idx = tid + it*256;      // 0..2047
            int row = idx >> 4, c4 = idx & 15;
            float4 v = *(const float4*)(Kbase + (long)(jt*BJ + row)*DK + c4*4);
            sKV[(c4*4+0)*SKT_STRIDE + row] = v.x;
            sKV[(c4*4+1)*SKT_STRIDE + row] = v.y;
            sKV[(c4*4+2)*SKT_STRIDE + row] = v.z;
            sKV[(c4*4+3)*SKT_STRIDE + row] = v.w;
        }
        __syncthreads();

        float acc[4][4] = {};
        #pragma unroll 8
        for (int kk = 0; kk < DK; ++kk) {
            float4 b4 = *(const float4*)(sKV + kk*SKT_STRIDE + tx*4);
            float a0 = sQ[(ty*4+0)*SQ_STRIDE + kk];
            float a1 = sQ[(ty*4+1)*SQ_STRIDE + kk];
            float a2 = sQ[(ty*4+2)*SQ_STRIDE + kk];
            float a3 = sQ[(ty*4+3)*SQ_STRIDE + kk];
            acc[0][0] += a0*b4.x; acc[0][1] += a0*b4.y; acc[0][2] += a0*b4.z; acc[0][3] += a0*b4.w;
            acc[1][0] += a1*b4.x; acc[1][1] += a1*b4.y; acc[1][2] += a1*b4.z; acc[1][3] += a1*b4.w;
            acc[2][0] += a2*b4.x; acc[2][1] += a2*b4.y; acc[2][2] += a2*b4.z; acc[2][3] += a2*b4.w;
            acc[3][0] += a3*b4.x; acc[3][1] += a3*b4.y; acc[3][2] += a3*b4.z; acc[3][3] += a3*b4.w;
        }
        int jl = jt*BJ + tx*4;
        #pragma unroll
        for (int r = 0; r < 4; ++r) {
            int gi = i0 + ty*4 + r;
            float4 u4 = *(const float4*)(utT + ((long)b*S + gi)*S + jl);
            float4 s4;
            s4.x = acc[r][0]*inv_scale*u4.x;
            s4.y = acc[r][1]*inv_scale*u4.y;
            s4.z = acc[r][2]*inv_scale*u4.z;
            s4.w = acc[r][3]*inv_scale*u4.w;
            *(float4*)(sS + (ty*4+r)*SS_STRIDE + jl) = s4;
        }
    }
    __syncthreads();

    // ---- per-row: softmax1 -> cumsum -> distance decay -> softmax2 ----
    const int wid = tid >> 5, lane = tid & 31;
    const float g  = gammas[h];
    const float gh = -log1pf(expf(g));           // -softplus(gamma)
    const int JMAX = TJn * BJ;
    const unsigned FULL = 0xffffffffu;

    #pragma unroll 1
    for (int q = 0; q < 4; ++q) {
        int r  = wid*4 + q;
        int gi = i0 + r;
        int L  = gi + 1;
        float* row = sS + r*SS_STRIDE;

        // zero tail so the output GEMM can run full tiles
        for (int j = L + lane; j < JMAX; j += 32) row[j] = 0.f;

        // pass 1: row max
        float mx = -INFINITY;
        for (int j = lane; j < L; j += 32) mx = fmaxf(mx, row[j]);
        #pragma unroll
        for (int o = 16; o > 0; o >>= 1) mx = fmaxf(mx, __shfl_xor_sync(FULL, mx, o));

        // pass 2: sum of exp
        float sm = 0.f;
        for (int j = lane; j < L; j += 32) sm += expf(row[j] - mx);
        #pragma unroll
        for (int o = 16; o > 0; o >>= 1) sm += __shfl_xor_sync(FULL, sm, o);
        float inv = 1.f / sm;

        // pass 3: inclusive scan of exp -> decay weights -> s2 = s * te
        float carry = 0.f, mx2 = -INFINITY;
        int nch = (L + 31) >> 5;
        for (int c = 0; c < nch; ++c) {
            int j = c*32 + lane;
            bool in = j < L;
            float s = in ? row[j] : 0.f;
            float e = in ? expf(s - mx) : 0.f;
            float v = e;
            #pragma unroll
            for (int o = 1; o < 32; o <<= 1) {
                float t = __shfl_up_sync(FULL, v, o);
                if (lane >= o) v += t;
            }
            float cum = carry + v;
            carry += __shfl_sync(FULL, v, 31);
            if (in) {
                float rem  = fmaxf(0.f, (sm - cum) * inv);
                float pe   = fabsf((float)(gi - j));
                float dist = sqrtf(rem * pe);
                float te   = expf(dist * gh);
                te = fminf(fmaxf(te, 1e-5f), 1e5f);
                float s2 = s * te;
                row[j] = s2;
                mx2 = fmaxf(mx2, s2);
            }
        }
        #pragma unroll
        for (int o = 16; o > 0; o >>= 1) mx2 = fmaxf(mx2, __shfl_xor_sync(FULL, mx2, o));

        // pass 4: second softmax denominator
        float sm2 = 0.f;
        for (int j = lane; j < L; j += 32) sm2 += expf(row[j] - mx2);
        #pragma unroll
        for (int o = 16; o > 0; o >>= 1) sm2 += __shfl_xor_sync(FULL, sm2, o);
        float inv2 = 1.f / sm2;

        // pass 5: final probabilities
        for (int j = lane; j < L; j += 32) row[j] = expf(row[j] - mx2) * inv2;
    }
    __syncthreads();

    // ---- output GEMM: out[i][d] = sum_j p[i][j] * v[j][d] ----
    const int tx2 = tid & 15;   // d group: d = tx2*4
    const int ty2 = tid >> 4;   // i group: i = ty2*2 + r
    float acc2[2][4] = {};

    for (int jt = 0; jt < TJn; ++jt) {
        __syncthreads();
        #pragma unroll
        for (int it = 0; it < 8; ++it) {
            int idx = tid + it*256;
            int row = idx >> 4, c4 = idx & 15;
            float4 v = *(const float4*)(Vbase + (long)(jt*BJ + row)*DK + c4*4);
            *(float4*)(sKV + row*SV_STRIDE + c4*4) = v;
        }
        __syncthreads();
        const float* p0 = sS + (ty2*2+0)*SS_STRIDE + jt*BJ;
        const float* p1 = sS + (ty2*2+1)*SS_STRIDE + jt*BJ;
        #pragma unroll 4
        for (int jj = 0; jj < BJ; ++jj) {
            float4 b4 = *(const float4*)(sKV + jj*SV_STRIDE + tx2*4);
            float a0 = p0[jj];
            float a1 = p1[jj];
            acc2[0][0] += a0*b4.x; acc2[0][1] += a0*b4.y; acc2[0][2] += a0*b4.z; acc2[0][3] += a0*b4.w;
            acc2[1][0] += a1*b4.x; acc2[1][1] += a1*b4.y; acc2[1][2] += a1*b4.z; acc2[1][3] += a1*b4.w;
        }
    }

    #pragma unroll
    for (int r = 0; r < 2; ++r) {
        int gi = i0 + ty2*2 + r;
        float4 v;
        v.x = acc2[r][0]; v.y = acc2[r][1]; v.z = acc2[r][2]; v.w = acc2[r][3];
        *(float4*)(g_attn + ((long)b*S + gi)*D + h*DK + tx2*4) = v;
    }
}

// ---------------------------------------------------------------------------
// Kernel 3: output projection.  out = g_attn @ Wo^T + bo  (plain [m][n]).
// ---------------------------------------------------------------------------
__global__ __launch_bounds__(256) void out_kernel(
    const float* __restrict__ Wo, const float* __restrict__ bo,
    float* __restrict__ out)
{
    __shared__ float sA[16*68];
    __shared__ float sB[16*68];

    const int m0 = blockIdx.y * 64;
    const int n0 = blockIdx.x * 64;
    const int tid = threadIdx.x;
    const int tx = tid & 15;
    const int ty = tid >> 4;
    const int lrow = tid >> 2;
    const int lc4  = tid & 3;

    float acc[4][4] = {};

    for (int k0 = 0; k0 < D; k0 += 16) {
        float4 av = *(const float4*)(g_attn + (long)(m0 + lrow)*D + k0 + lc4*4);
        float4 bw = *(const float4*)(Wo     + (long)(n0 + lrow)*D + k0 + lc4*4);
        __syncthreads();
        sA[(lc4*4+0)*68 + lrow] = av.x;
        sA[(lc4*4+1)*68 + lrow] = av.y;
        sA[(lc4*4+2)*68 + lrow] = av.z;
        sA[(lc4*4+3)*68 + lrow] = av.w;
        sB[(lc4*4+0)*68 + lrow] = bw.x;
        sB[(lc4*4+1)*68 + lrow] = bw.y;
        sB[(lc4*4+2)*68 + lrow] = bw.z;
        sB[(lc4*4+3)*68 + lrow] = bw.w;
        __syncthreads();
        #pragma unroll
        for (int kk = 0; kk < 16; ++kk) {
            float4 a4 = *(const float4*)(sA + kk*68 + ty*4);
            float4 b4 = *(const float4*)(sB + kk*68 + tx*4);
            acc[0][0] += a4.x*b4.x; acc[0][1] += a4.x*b4.y; acc[0][2] += a4.x*b4.z; acc[0][3] += a4.x*b4.w;
            acc[1][0] += a4.y*b4.x; acc[1][1] += a4.y*b4.y; acc[1][2] += a4.y*b4.z; acc[1][3] += a4.y*b4.w;
            acc[2][0] += a4.z*b4.x; acc[2][1] += a4.z*b4.y; acc[2][2] += a4.z*b4.z; acc[2][3] += a4.z*b4.w;
            acc[3][0] += a4.w*b4.x; acc[3][1] += a4.w*b4.y; acc[3][2] += a4.w*b4.z; acc[3][3] += a4.w*b4.w;
        }
    }

    const int n = n0 + tx*4;
    float4 bia = *(const float4*)(bo + n);
    #pragma unroll
    for (int r = 0; r < 4; ++r) {
        int m = m0 + ty*4 + r;
        float4 v;
        v.x = acc[r][0] + bia.x;
        v.y = acc[r][1] + bia.y;
        v.z = acc[r][2] + bia.z;
        v.w = acc[r][3] + bia.w;
        *(float4*)(out + (long)m*D + n) = v;
    }
}

// ---------------------------------------------------------------------------
extern "C" void kernel_launch(void* const* d_in, const int* in_sizes, int n_in,
                              void* d_out, int out_size)
{
    const float* x      = (const float*)d_in[0];
    const float* utT    = (const float*)d_in[1];
    const float* Wk     = (const float*)d_in[2];
    const float* bk     = (const float*)d_in[3];
    const float* Wv     = (const float*)d_in[4];
    const float* bv     = (const float*)d_in[5];
    const float* Wo     = (const float*)d_in[6];
    const float* bo     = (const float*)d_in[7];
    const float* gammas = (const float*)d_in[8];
    float* out = (float*)d_out;

    // QK + V projections (z selects which weight)
    proj_kernel<<<dim3(D/64, (B*S)/64, 2), 256>>>(x, Wk, bk, Wv, bv);

    // attention
    size_t smem_bytes = (size_t)(TM*SS_STRIDE + TM*SQ_STRIDE + BJ*SV_STRIDE) * sizeof(float);
    cudaFuncSetAttribute(attn_kernel, cudaFuncAttributeMaxDynamicSharedMemorySize, (int)smem_bytes);
    attn_kernel<<<dim3(S/TM, H, B), 256, smem_bytes>>>(utT, gammas);

    // output projection
    out_kernel<<<dim3(D/64, (B*S)/64), 256>>>(Wo, bo, out);
}